// round 11
// baseline (speedup 1.0000x reference)
#include <cuda_runtime.h>

// ---------------------------------------------------------------------------
// IMEX-ETD: CG-solve (I - DT*D*Lap_neumann) x = u, then pointwise ETD update.
// Round 11: moment-based Krylov CG. The 3-step CG trajectory lives in
// span{r0, A r0, A^2 r0}; all CG scalars are bilinear forms in the moments
// m_ij = (A^i r0, A^j r0), i<=2, j<=3. Structure:
//   P1: r0 = DT*D*lap(u), s0 = A r0 (composed 2-hop)   -> m00,m01,m11
//   P2: t = A s0, v = A t (composed 2-hop; v in regs)  -> m02,m12,m22,m03,m13,m23
//   scalar CG trajectory from moments (double, deterministic, no symmetry
//   assumptions) -> coefficients; epilogue: out = ETD(u + c0 r0 + c1 s0 + c2 t)
// 13N total traffic, 2 grid barriers, fixed pass count.
// ---------------------------------------------------------------------------

#define N_ELEM   8388608     // 8 * 1 * 1024 * 1024
#define N4       2097152     // float4 count
#define ROW4     256         // float4s per row
#define GBLK     152
#define TBLK     1024
#define NTHREADS (GBLK * TBLK)

#define DT_C     0.1f
#define CG_TAU   0.015

__device__ float g_r0[N_ELEM];
__device__ float g_s0[N_ELEM];
__device__ float g_t [N_ELEM];

__device__ double g_m1[3][GBLK];   // m00, m01, m11
__device__ double g_m2[6][GBLK];   // m02, m12, m22, m03, m13, m23

__device__ unsigned g_cnt = 0;
__device__ volatile unsigned g_gen = 0;

// ---------------------------------------------------------------------------

__device__ __forceinline__ void grid_bar() {
    __syncthreads();
    __threadfence();                       // release
    if (threadIdx.x == 0) {
        unsigned snap = g_gen;
        unsigned arrived = atomicAdd(&g_cnt, 1u);
        if (arrived == GBLK - 1) {
            g_cnt = 0;
            __threadfence();
            g_gen = snap + 1u;
        } else {
            while (g_gen == snap) { }
        }
    }
    __syncthreads();
    __threadfence();                       // acquire (CCTL.IVALL): L1 coherent
}

__device__ __forceinline__ double block_reduce_d(double v) {
    __shared__ double sh[32];
    int lane = threadIdx.x & 31;
    int w    = threadIdx.x >> 5;
#pragma unroll
    for (int o = 16; o; o >>= 1) v += __shfl_down_sync(0xffffffffu, v, o);
    if (lane == 0) sh[w] = v;
    __syncthreads();
    if (w == 0) {
        v = sh[lane];
#pragma unroll
        for (int o = 16; o; o >>= 1) v += __shfl_down_sync(0xffffffffu, v, o);
    }
    return v;
}

__device__ __forceinline__ double sum_partials_d(const double* a) {
    __shared__ double tot;
    int t = threadIdx.x;
    if (t < 32) {
        double s = 0.0;
#pragma unroll
        for (int j = t; j < GBLK; j += 32) s += a[j];
#pragma unroll
        for (int o = 16; o; o >>= 1) s += __shfl_down_sync(0xffffffffu, s, o);
        if (t == 0) tot = s;
    }
    __syncthreads();
    return tot;
}

// ---------------------------------------------------------------------------

__device__ __forceinline__ float dot4f(float4 a, float4 b) {
    return fmaf(a.x, b.x, fmaf(a.y, b.y, fmaf(a.z, b.z, a.w * b.w)));
}

__device__ __forceinline__ float4 lap_mk(float4 c, float4 t, float4 b,
                                         float lf, float rt) {
    float4 L;
    L.x = fmaf(-4.0f, c.x, (lf  + c.y) + (t.x + b.x));
    L.y = fmaf(-4.0f, c.y, (c.x + c.z) + (t.y + b.y));
    L.z = fmaf(-4.0f, c.z, (c.y + c.w) + (t.z + b.z));
    L.w = fmaf(-4.0f, c.w, (c.z + rt ) + (t.w + b.w));
    return L;
}

// r0 = DT * D * lap(u) at float4 index j (input path)
__device__ __forceinline__ float4 r0_vec(const float* __restrict__ u,
                                         const float* __restrict__ D, int j) {
    int x4 = j & (ROW4 - 1);
    int y  = (j >> 8) & 1023;
    const float4* u4 = (const float4*)u;
    float4 c = __ldg(u4 + j);
    float4 t = (y > 0)    ? __ldg(u4 + (j - ROW4)) : c;
    float4 b = (y < 1023) ? __ldg(u4 + (j + ROW4)) : c;
    float lf = (x4 > 0)        ? __ldg(u + 4*j - 1) : c.x;
    float rt = (x4 < ROW4 - 1) ? __ldg(u + 4*j + 4) : c.w;
    float4 dd = __ldg(((const float4*)D) + j);
    float4 lp = lap_mk(c, t, b, lf, rt);
    float4 rv;
    rv.x = DT_C * dd.x * lp.x;
    rv.y = DT_C * dd.y * lp.y;
    rv.z = DT_C * dd.z * lp.z;
    rv.w = DT_C * dd.w * lp.w;
    return rv;
}

__device__ __forceinline__ float r0_scalar(const float* __restrict__ u,
                                           const float* __restrict__ D, int i) {
    int x = i & 1023;
    int y = (i >> 10) & 1023;
    float c = __ldg(&u[i]);
    float l = (x > 0)    ? __ldg(&u[i - 1])    : c;
    float r = (x < 1023) ? __ldg(&u[i + 1])    : c;
    float t = (y > 0)    ? __ldg(&u[i - 1024]) : c;
    float b = (y < 1023) ? __ldg(&u[i + 1024]) : c;
    return DT_C * __ldg(&D[i]) * fmaf(-4.0f, c, (l + r) + (t + b));
}

// (A y)_j = y_j - DT*D_j*lap(y)_j  (vector, global-load laterals)
__device__ __forceinline__ float4 A_vec(const float* __restrict__ y,
                                        const float* __restrict__ D, int j) {
    int x4 = j & (ROW4 - 1);
    int yy = (j >> 8) & 1023;
    const float4* y4 = (const float4*)y;
    float4 c = y4[j];
    float4 t = (yy > 0)    ? y4[j - ROW4] : c;
    float4 b = (yy < 1023) ? y4[j + ROW4] : c;
    float lf = (x4 > 0)        ? y[4*j - 1] : c.x;
    float rt = (x4 < ROW4 - 1) ? y[4*j + 4] : c.w;
    float4 dd = __ldg(((const float4*)D) + j);
    float4 lp = lap_mk(c, t, b, lf, rt);
    float4 r;
    r.x = fmaf(-DT_C * dd.x, lp.x, c.x);
    r.y = fmaf(-DT_C * dd.y, lp.y, c.y);
    r.z = fmaf(-DT_C * dd.z, lp.z, c.z);
    r.w = fmaf(-DT_C * dd.w, lp.w, c.w);
    return r;
}

__device__ __forceinline__ float A_scalar(const float* __restrict__ y,
                                          const float* __restrict__ D, int i) {
    int x = i & 1023;
    int yy = (i >> 10) & 1023;
    float c = y[i];
    float l = (x > 0)     ? y[i - 1]    : c;
    float r = (x < 1023)  ? y[i + 1]    : c;
    float t = (yy > 0)    ? y[i - 1024] : c;
    float b = (yy < 1023) ? y[i + 1024] : c;
    return fmaf(-DT_C * __ldg(&D[i]), fmaf(-4.0f, c, (l + r) + (t + b)), c);
}

// ---------------------------------------------------------------------------

__global__ void __launch_bounds__(TBLK, 1)
imexetd_cg_kernel(const float* __restrict__ u,
                  const float* __restrict__ D,
                  const float* __restrict__ kp,
                  const float* __restrict__ aCp,
                  const float* __restrict__ Ctp,
                  float* __restrict__ out)
{
    const int tid  = blockIdx.x * TBLK + threadIdx.x;
    const int lane = threadIdx.x & 31;
    const float4* __restrict__ D4 = (const float4*)D;

    // ========== P1: r0 = DT*D*lap(u); s0 = A r0; m00, m01, m11 ==========
    {
        float4* __restrict__ r4w = (float4*)g_r0;
        float4* __restrict__ s4w = (float4*)g_s0;
        double a00 = 0.0, a01 = 0.0, a11 = 0.0;
        for (int j = tid; j < N4; j += NTHREADS) {
            int x4 = j & (ROW4 - 1);
            int y  = (j >> 8) & 1023;
            float4 rc = r0_vec(u, D, j);
            float4 rT = (y > 0)    ? r0_vec(u, D, j - ROW4) : rc;
            float4 rB = (y < 1023) ? r0_vec(u, D, j + ROW4) : rc;
            float rL = __shfl_up_sync(0xffffffffu, rc.w, 1);
            float rR = __shfl_down_sync(0xffffffffu, rc.x, 1);
            if (lane == 0)
                rL = (x4 > 0) ? r0_scalar(u, D, 4*j - 1) : rc.x;
            if (lane == 31)
                rR = (x4 < ROW4 - 1) ? r0_scalar(u, D, 4*j + 4) : rc.w;
            float4 dd = __ldg(D4 + j);
            float4 lp = lap_mk(rc, rT, rB, rL, rR);
            float4 sv;
            sv.x = fmaf(-DT_C * dd.x, lp.x, rc.x);
            sv.y = fmaf(-DT_C * dd.y, lp.y, rc.y);
            sv.z = fmaf(-DT_C * dd.z, lp.z, rc.z);
            sv.w = fmaf(-DT_C * dd.w, lp.w, rc.w);
            r4w[j] = rc;
            s4w[j] = sv;
            a00 += (double)dot4f(rc, rc);
            a01 += (double)dot4f(rc, sv);
            a11 += (double)dot4f(sv, sv);
        }
        double v;
        v = block_reduce_d(a00);
        if (threadIdx.x == 0) g_m1[0][blockIdx.x] = v;
        __syncthreads();
        v = block_reduce_d(a01);
        if (threadIdx.x == 0) g_m1[1][blockIdx.x] = v;
        __syncthreads();
        v = block_reduce_d(a11);
        if (threadIdx.x == 0) g_m1[2][blockIdx.x] = v;
    }
    grid_bar();                            // r0, s0, m1 partials visible

    // ========== P2: t = A s0; v = A t (regs); m02,m12,m22,m03,m13,m23 =====
    {
        const float*  __restrict__ s0f = (const float*)g_s0;
        const float4* __restrict__ s04 = (const float4*)g_s0;
        const float4* __restrict__ r04 = (const float4*)g_r0;
        float4* __restrict__ t4w = (float4*)g_t;
        double a02 = 0.0, a12 = 0.0, a22 = 0.0;
        double a03 = 0.0, a13 = 0.0, a23 = 0.0;

        for (int j = tid; j < N4; j += NTHREADS) {
            int x4 = j & (ROW4 - 1);
            int y  = (j >> 8) & 1023;

            // t at j (shuffle laterals)
            float4 sC = s04[j];
            float4 sT = (y > 0)    ? s04[j - ROW4] : sC;
            float4 sB = (y < 1023) ? s04[j + ROW4] : sC;
            float sL = __shfl_up_sync(0xffffffffu, sC.w, 1);
            float sR = __shfl_down_sync(0xffffffffu, sC.x, 1);
            if (lane == 0)
                sL = (x4 > 0) ? s0f[4*j - 1] : sC.x;
            if (lane == 31)
                sR = (x4 < ROW4 - 1) ? s0f[4*j + 4] : sC.w;
            float4 dd = __ldg(D4 + j);
            float4 lp = lap_mk(sC, sT, sB, sL, sR);
            float4 tC;
            tC.x = fmaf(-DT_C * dd.x, lp.x, sC.x);
            tC.y = fmaf(-DT_C * dd.y, lp.y, sC.y);
            tC.z = fmaf(-DT_C * dd.z, lp.z, sC.z);
            tC.w = fmaf(-DT_C * dd.w, lp.w, sC.w);

            // t at neighbor rows (recompute; loads CSE against sT/sB)
            float4 tT = (y > 0)    ? A_vec(s0f, D, j - ROW4) : tC;
            float4 tB = (y < 1023) ? A_vec(s0f, D, j + ROW4) : tC;
            float tL = __shfl_up_sync(0xffffffffu, tC.w, 1);
            float tR = __shfl_down_sync(0xffffffffu, tC.x, 1);
            if (lane == 0)
                tL = (x4 > 0) ? A_scalar(s0f, D, 4*j - 1) : tC.x;
            if (lane == 31)
                tR = (x4 < ROW4 - 1) ? A_scalar(s0f, D, 4*j + 4) : tC.w;

            // v = A t at j
            float4 lt = lap_mk(tC, tT, tB, tL, tR);
            float4 vv;
            vv.x = fmaf(-DT_C * dd.x, lt.x, tC.x);
            vv.y = fmaf(-DT_C * dd.y, lt.y, tC.y);
            vv.z = fmaf(-DT_C * dd.z, lt.z, tC.z);
            vv.w = fmaf(-DT_C * dd.w, lt.w, tC.w);

            float4 r0v = r04[j];
            t4w[j] = tC;

            a02 += (double)dot4f(r0v, tC);
            a12 += (double)dot4f(sC,  tC);
            a22 += (double)dot4f(tC,  tC);
            a03 += (double)dot4f(r0v, vv);
            a13 += (double)dot4f(sC,  vv);
            a23 += (double)dot4f(tC,  vv);
        }
        double acc[6] = {a02, a12, a22, a03, a13, a23};
#pragma unroll
        for (int q = 0; q < 6; q++) {
            double v = block_reduce_d(acc[q]);
            if (threadIdx.x == 0) g_m2[q][blockIdx.x] = v;
            __syncthreads();
        }
    }
    grid_bar();                            // t, m2 partials visible

    // ========== scalar CG trajectory from moments (deterministic) =========
    double m00 = sum_partials_d(g_m1[0]);
    double m01 = sum_partials_d(g_m1[1]);
    double m11 = sum_partials_d(g_m1[2]);
    double m02 = sum_partials_d(g_m2[0]);
    double m12 = sum_partials_d(g_m2[1]);
    double m22 = sum_partials_d(g_m2[2]);
    double m03 = sum_partials_d(g_m2[3]);
    double m13 = sum_partials_d(g_m2[4]);
    double m23 = sum_partials_d(g_m2[5]);

    double M[4][4];
    M[0][0] = m00; M[0][1] = m01; M[0][2] = m02; M[0][3] = m03;
    M[1][0] = m01; M[1][1] = m11; M[1][2] = m12; M[1][3] = m13;
    M[2][0] = m02; M[2][1] = m12; M[2][2] = m22; M[2][3] = m23;
    M[3][0] = m03; M[3][1] = m13; M[3][2] = m23; M[3][3] = 0.0;  // never used

    double rv[4] = {1.0, 0.0, 0.0, 0.0};
    double pv[4] = {1.0, 0.0, 0.0, 0.0};
    double xv[4] = {0.0, 0.0, 0.0, 0.0};
    double rs = m00;

    for (int step = 0; step < 3; step++) {
        double Apv[4] = {0.0, pv[0], pv[1], pv[2]};   // A shifts Krylov index
        double pAp = 0.0;
#pragma unroll
        for (int i = 0; i < 4; i++)
#pragma unroll
            for (int jq = 0; jq < 4; jq++)
                pAp += pv[i] * M[i][jq] * Apv[jq];
        float af = (float)(rs / (pAp + 1e-300));
        double ad = (double)af;
#pragma unroll
        for (int i = 0; i < 4; i++) {
            xv[i] += ad * pv[i];
            rv[i] -= ad * Apv[i];
        }
        if (step == 2) break;              // rv now degree 3; stop (m33 unknown)
        double rs_new = 0.0;
#pragma unroll
        for (int i = 0; i < 4; i++)
#pragma unroll
            for (int jq = 0; jq < 4; jq++)
                rs_new += rv[i] * M[i][jq] * rv[jq];
        if (rs_new < 0.0) rs_new = 0.0;
        if (sqrt(rs_new) < CG_TAU) break;
        float bf = (float)(rs_new / (rs + 1e-300));
        double bd = (double)bf;
#pragma unroll
        for (int i = 0; i < 4; i++) pv[i] = rv[i] + bd * pv[i];
        rs = rs_new;
    }
    float c0 = (float)xv[0];
    float c1 = (float)xv[1];
    float c2 = (float)xv[2];

    // ========== epilogue: u_tilde = u + c0 r0 + c1 s0 + c2 t; ETD =========
    float kk = __ldg(&kp[0]);
    float a  = kk - __ldg(&aCp[0]) * __ldg(&Ctp[0]);
    float bc = kk;                               // k / K_CAP, K_CAP = 1
    float adc = fminf(fmaxf(a * DT_C, -60.0f), 60.0f);
    float e   = expf(adc);
    float em1 = e - 1.0f;

    const float4* __restrict__ u4  = (const float4*)u;
    const float4* __restrict__ r04 = (const float4*)g_r0;
    const float4* __restrict__ s04 = (const float4*)g_s0;
    const float4* __restrict__ t4  = (const float4*)g_t;
    float4* __restrict__ o4 = (float4*)out;

    for (int j = tid; j < N4; j += NTHREADS) {
        float4 ut = __ldg(u4 + j);
        float4 rv0 = r04[j];
        float4 sv0 = s04[j];
        float4 tv0 = t4[j];
        ut.x = fmaf(c0, rv0.x, ut.x);
        ut.y = fmaf(c0, rv0.y, ut.y);
        ut.z = fmaf(c0, rv0.z, ut.z);
        ut.w = fmaf(c0, rv0.w, ut.w);
        ut.x = fmaf(c1, sv0.x, ut.x);
        ut.y = fmaf(c1, sv0.y, ut.y);
        ut.z = fmaf(c1, sv0.z, ut.z);
        ut.w = fmaf(c1, sv0.w, ut.w);
        ut.x = fmaf(c2, tv0.x, ut.x);
        ut.y = fmaf(c2, tv0.y, ut.y);
        ut.z = fmaf(c2, tv0.z, ut.z);
        ut.w = fmaf(c2, tv0.w, ut.w);

        float4 un;
        {
            float num = a * ut.x * e;
            float den = fmaf(bc * ut.x, em1, a);
            un.x = (fabsf(den) > 1e-12f) ? (num / den) : ut.x;
            num = a * ut.y * e;
            den = fmaf(bc * ut.y, em1, a);
            un.y = (fabsf(den) > 1e-12f) ? (num / den) : ut.y;
            num = a * ut.z * e;
            den = fmaf(bc * ut.z, em1, a);
            un.z = (fabsf(den) > 1e-12f) ? (num / den) : ut.z;
            num = a * ut.w * e;
            den = fmaf(bc * ut.w, em1, a);
            un.w = (fabsf(den) > 1e-12f) ? (num / den) : ut.w;
        }
        un.x = fminf(fmaxf(un.x, 0.0f), 1.0f);
        un.y = fminf(fmaxf(un.y, 0.0f), 1.0f);
        un.z = fminf(fmaxf(un.z, 0.0f), 1.0f);
        un.w = fminf(fmaxf(un.w, 0.0f), 1.0f);
        o4[j] = un;
    }
}

// ---------------------------------------------------------------------------

extern "C" void kernel_launch(void* const* d_in, const int* in_sizes, int n_in,
                              void* d_out, int out_size)
{
    const float* u   = (const float*)d_in[0];
    const float* D   = (const float*)d_in[1];
    const float* k   = (const float*)d_in[2];
    const float* aC  = (const float*)d_in[3];
    const float* C_t = (const float*)d_in[4];
    float* out = (float*)d_out;

    imexetd_cg_kernel<<<GBLK, TBLK>>>(u, D, k, aC, C_t, out);
}

// round 12
// speedup vs baseline: 1.0129x; 1.0129x over previous
#include <cuda_runtime.h>

// ---------------------------------------------------------------------------
// IMEX-ETD: CG-solve (I - DT*D*Lap_neumann) x = u, then pointwise ETD update.
// Round 12: moment-based Krylov CG (round 11 algebra) computed with FOUR
// SIMPLE single-stencil passes (the pass shape measured fastest, 5.7 TB/s in
// round 2) instead of composed 2-hop fusions:
//   P1: r0 = DT*D*lap(u)            -> m00
//   P2: s0 = A r0                   -> m01, m11
//   P3: t  = A s0                   -> m12, m22
//   P4: v  = A t (registers only)   -> m02, m03, m13, m23
//   scalar 3-step CG trajectory from moments -> c0,c1,c2
//   epilogue: out = ETD(u + c0 r0 + c1 s0 + c2 t)
// 18N total traffic, 4 grid barriers, fixed pass count, fully deterministic.
// ---------------------------------------------------------------------------

#define N_ELEM   8388608     // 8 * 1 * 1024 * 1024
#define N4       2097152     // float4 count
#define ROW4     256         // float4s per row
#define GBLK     152
#define TBLK     1024
#define NTHREADS (GBLK * TBLK)

#define DT_C     0.1f
#define CG_TAU   0.015

__device__ float g_r0[N_ELEM];
__device__ float g_s0[N_ELEM];
__device__ float g_t [N_ELEM];

// moment partials: 0:m00 1:m01 2:m11 3:m12 4:m22 5:m02 6:m03 7:m13 8:m23
__device__ double g_pm[9][GBLK];

__device__ unsigned g_cnt = 0;
__device__ volatile unsigned g_gen = 0;

// ---------------------------------------------------------------------------

__device__ __forceinline__ void grid_bar() {
    __syncthreads();
    __threadfence();                       // release
    if (threadIdx.x == 0) {
        unsigned snap = g_gen;
        unsigned arrived = atomicAdd(&g_cnt, 1u);
        if (arrived == GBLK - 1) {
            g_cnt = 0;
            __threadfence();
            g_gen = snap + 1u;
        } else {
            while (g_gen == snap) { }
        }
    }
    __syncthreads();
    __threadfence();                       // acquire (CCTL.IVALL): L1 coherent
}

__device__ __forceinline__ double block_reduce_d(double v) {
    __shared__ double sh[32];
    int lane = threadIdx.x & 31;
    int w    = threadIdx.x >> 5;
#pragma unroll
    for (int o = 16; o; o >>= 1) v += __shfl_down_sync(0xffffffffu, v, o);
    if (lane == 0) sh[w] = v;
    __syncthreads();
    if (w == 0) {
        v = sh[lane];
#pragma unroll
        for (int o = 16; o; o >>= 1) v += __shfl_down_sync(0xffffffffu, v, o);
    }
    return v;
}

__device__ __forceinline__ double sum_partials_d(const double* a) {
    __shared__ double tot;
    int t = threadIdx.x;
    if (t < 32) {
        double s = 0.0;
#pragma unroll
        for (int j = t; j < GBLK; j += 32) s += a[j];
#pragma unroll
        for (int o = 16; o; o >>= 1) s += __shfl_down_sync(0xffffffffu, s, o);
        if (t == 0) tot = s;
    }
    __syncthreads();
    return tot;
}

// ---------------------------------------------------------------------------

__device__ __forceinline__ float dot4f(float4 a, float4 b) {
    return fmaf(a.x, b.x, fmaf(a.y, b.y, fmaf(a.z, b.z, a.w * b.w)));
}

__device__ __forceinline__ float4 lap_mk(float4 c, float4 t, float4 b,
                                         float lf, float rt) {
    float4 L;
    L.x = fmaf(-4.0f, c.x, (lf  + c.y) + (t.x + b.x));
    L.y = fmaf(-4.0f, c.y, (c.x + c.z) + (t.y + b.y));
    L.z = fmaf(-4.0f, c.z, (c.y + c.w) + (t.z + b.z));
    L.w = fmaf(-4.0f, c.w, (c.z + rt ) + (t.w + b.w));
    return L;
}

// 5-point window at float4 index j (Neumann edge clamp), plain cached loads
struct Win { float4 c, t, b; float l, r; };

__device__ __forceinline__ Win load_win(const float* __restrict__ s, int j) {
    Win w;
    int x4 = j & (ROW4 - 1);
    int y  = (j >> 8) & 1023;
    const float4* s4 = (const float4*)s;
    w.c = s4[j];
    w.t = (y > 0)    ? s4[j - ROW4] : w.c;
    w.b = (y < 1023) ? s4[j + ROW4] : w.c;
    w.l = (x4 > 0)        ? s[4*j - 1] : w.c.x;
    w.r = (x4 < ROW4 - 1) ? s[4*j + 4] : w.c.w;
    return w;
}

// ---------------------------------------------------------------------------

__global__ void __launch_bounds__(TBLK, 1)
imexetd_cg_kernel(const float* __restrict__ u,
                  const float* __restrict__ D,
                  const float* __restrict__ kp,
                  const float* __restrict__ aCp,
                  const float* __restrict__ Ctp,
                  float* __restrict__ out)
{
    const int tid = blockIdx.x * TBLK + threadIdx.x;
    const float4* __restrict__ D4 = (const float4*)D;

    // ================= P1: r0 = DT*D*lap(u); m00 ==========================
    {
        float4* __restrict__ dst = (float4*)g_r0;
        double a00 = 0.0;
        for (int j = tid; j < N4; j += NTHREADS) {
            Win w = load_win(u, j);
            float4 dd = __ldg(D4 + j);
            float4 lp = lap_mk(w.c, w.t, w.b, w.l, w.r);
            float4 rv;
            rv.x = DT_C * dd.x * lp.x;
            rv.y = DT_C * dd.y * lp.y;
            rv.z = DT_C * dd.z * lp.z;
            rv.w = DT_C * dd.w * lp.w;
            dst[j] = rv;
            a00 += (double)dot4f(rv, rv);
        }
        double v = block_reduce_d(a00);
        if (threadIdx.x == 0) g_pm[0][blockIdx.x] = v;
    }
    grid_bar();

    // ================= P2: s0 = A r0; m01, m11 ============================
    {
        float4* __restrict__ dst = (float4*)g_s0;
        double a01 = 0.0, a11 = 0.0;
        for (int j = tid; j < N4; j += NTHREADS) {
            Win w = load_win(g_r0, j);
            float4 dd = __ldg(D4 + j);
            float4 lp = lap_mk(w.c, w.t, w.b, w.l, w.r);
            float4 sv;
            sv.x = fmaf(-DT_C * dd.x, lp.x, w.c.x);
            sv.y = fmaf(-DT_C * dd.y, lp.y, w.c.y);
            sv.z = fmaf(-DT_C * dd.z, lp.z, w.c.z);
            sv.w = fmaf(-DT_C * dd.w, lp.w, w.c.w);
            dst[j] = sv;
            a01 += (double)dot4f(w.c, sv);
            a11 += (double)dot4f(sv, sv);
        }
        double v0 = block_reduce_d(a01);
        __syncthreads();
        double v1 = block_reduce_d(a11);
        if (threadIdx.x == 0) {
            g_pm[1][blockIdx.x] = v0;
            g_pm[2][blockIdx.x] = v1;
        }
    }
    grid_bar();

    // ================= P3: t = A s0; m12, m22 =============================
    {
        float4* __restrict__ dst = (float4*)g_t;
        double a12 = 0.0, a22 = 0.0;
        for (int j = tid; j < N4; j += NTHREADS) {
            Win w = load_win(g_s0, j);
            float4 dd = __ldg(D4 + j);
            float4 lp = lap_mk(w.c, w.t, w.b, w.l, w.r);
            float4 tv;
            tv.x = fmaf(-DT_C * dd.x, lp.x, w.c.x);
            tv.y = fmaf(-DT_C * dd.y, lp.y, w.c.y);
            tv.z = fmaf(-DT_C * dd.z, lp.z, w.c.z);
            tv.w = fmaf(-DT_C * dd.w, lp.w, w.c.w);
            dst[j] = tv;
            a12 += (double)dot4f(w.c, tv);
            a22 += (double)dot4f(tv, tv);
        }
        double v0 = block_reduce_d(a12);
        __syncthreads();
        double v1 = block_reduce_d(a22);
        if (threadIdx.x == 0) {
            g_pm[3][blockIdx.x] = v0;
            g_pm[4][blockIdx.x] = v1;
        }
    }
    grid_bar();

    // ========= P4: v = A t (registers); m02, m03, m13, m23 ================
    {
        const float4* __restrict__ r04 = (const float4*)g_r0;
        const float4* __restrict__ s04 = (const float4*)g_s0;
        double a02 = 0.0, a03 = 0.0, a13 = 0.0, a23 = 0.0;
        for (int j = tid; j < N4; j += NTHREADS) {
            Win w = load_win(g_t, j);
            float4 dd = __ldg(D4 + j);
            float4 lp = lap_mk(w.c, w.t, w.b, w.l, w.r);
            float4 vv;
            vv.x = fmaf(-DT_C * dd.x, lp.x, w.c.x);
            vv.y = fmaf(-DT_C * dd.y, lp.y, w.c.y);
            vv.z = fmaf(-DT_C * dd.z, lp.z, w.c.z);
            vv.w = fmaf(-DT_C * dd.w, lp.w, w.c.w);
            float4 r0v = r04[j];
            float4 s0v = s04[j];
            a02 += (double)dot4f(r0v, w.c);
            a03 += (double)dot4f(r0v, vv);
            a13 += (double)dot4f(s0v, vv);
            a23 += (double)dot4f(w.c, vv);
        }
        double v0 = block_reduce_d(a02);
        __syncthreads();
        double v1 = block_reduce_d(a03);
        __syncthreads();
        double v2 = block_reduce_d(a13);
        __syncthreads();
        double v3 = block_reduce_d(a23);
        if (threadIdx.x == 0) {
            g_pm[5][blockIdx.x] = v0;
            g_pm[6][blockIdx.x] = v1;
            g_pm[7][blockIdx.x] = v2;
            g_pm[8][blockIdx.x] = v3;
        }
    }
    grid_bar();

    // ========== scalar CG trajectory from moments (deterministic) =========
    double m00 = sum_partials_d(g_pm[0]);
    double m01 = sum_partials_d(g_pm[1]);
    double m11 = sum_partials_d(g_pm[2]);
    double m12 = sum_partials_d(g_pm[3]);
    double m22 = sum_partials_d(g_pm[4]);
    double m02 = sum_partials_d(g_pm[5]);
    double m03 = sum_partials_d(g_pm[6]);
    double m13 = sum_partials_d(g_pm[7]);
    double m23 = sum_partials_d(g_pm[8]);

    double M[4][4];
    M[0][0] = m00; M[0][1] = m01; M[0][2] = m02; M[0][3] = m03;
    M[1][0] = m01; M[1][1] = m11; M[1][2] = m12; M[1][3] = m13;
    M[2][0] = m02; M[2][1] = m12; M[2][2] = m22; M[2][3] = m23;
    M[3][0] = m03; M[3][1] = m13; M[3][2] = m23; M[3][3] = 0.0;  // never used

    double rv[4] = {1.0, 0.0, 0.0, 0.0};
    double pv[4] = {1.0, 0.0, 0.0, 0.0};
    double xv[4] = {0.0, 0.0, 0.0, 0.0};
    double rs = m00;

    for (int step = 0; step < 3; step++) {
        double Apv[4] = {0.0, pv[0], pv[1], pv[2]};   // A shifts Krylov index
        double pAp = 0.0;
#pragma unroll
        for (int i = 0; i < 4; i++)
#pragma unroll
            for (int jq = 0; jq < 4; jq++)
                pAp += pv[i] * M[i][jq] * Apv[jq];
        float af = (float)(rs / (pAp + 1e-300));
        double ad = (double)af;
#pragma unroll
        for (int i = 0; i < 4; i++) {
            xv[i] += ad * pv[i];
            rv[i] -= ad * Apv[i];
        }
        if (step == 2) break;              // rv degree 3; m33 unknown -> stop
        double rs_new = 0.0;
#pragma unroll
        for (int i = 0; i < 4; i++)
#pragma unroll
            for (int jq = 0; jq < 4; jq++)
                rs_new += rv[i] * M[i][jq] * rv[jq];
        if (rs_new < 0.0) rs_new = 0.0;
        if (sqrt(rs_new) < CG_TAU) break;
        float bf = (float)(rs_new / (rs + 1e-300));
        double bd = (double)bf;
#pragma unroll
        for (int i = 0; i < 4; i++) pv[i] = rv[i] + bd * pv[i];
        rs = rs_new;
    }
    float c0 = (float)xv[0];
    float c1 = (float)xv[1];
    float c2 = (float)xv[2];

    // ========== epilogue: u_tilde = u + c0 r0 + c1 s0 + c2 t; ETD =========
    float kk = __ldg(&kp[0]);
    float a  = kk - __ldg(&aCp[0]) * __ldg(&Ctp[0]);
    float bc = kk;                               // k / K_CAP, K_CAP = 1
    float adc = fminf(fmaxf(a * DT_C, -60.0f), 60.0f);
    float e   = expf(adc);
    float em1 = e - 1.0f;

    const float4* __restrict__ u4  = (const float4*)u;
    const float4* __restrict__ r04 = (const float4*)g_r0;
    const float4* __restrict__ s04 = (const float4*)g_s0;
    const float4* __restrict__ t4  = (const float4*)g_t;
    float4* __restrict__ o4 = (float4*)out;

    for (int j = tid; j < N4; j += NTHREADS) {
        float4 ut = __ldg(u4 + j);
        float4 rv0 = r04[j];
        float4 sv0 = s04[j];
        float4 tv0 = t4[j];
        ut.x = fmaf(c0, rv0.x, ut.x);
        ut.y = fmaf(c0, rv0.y, ut.y);
        ut.z = fmaf(c0, rv0.z, ut.z);
        ut.w = fmaf(c0, rv0.w, ut.w);
        ut.x = fmaf(c1, sv0.x, ut.x);
        ut.y = fmaf(c1, sv0.y, ut.y);
        ut.z = fmaf(c1, sv0.z, ut.z);
        ut.w = fmaf(c1, sv0.w, ut.w);
        ut.x = fmaf(c2, tv0.x, ut.x);
        ut.y = fmaf(c2, tv0.y, ut.y);
        ut.z = fmaf(c2, tv0.z, ut.z);
        ut.w = fmaf(c2, tv0.w, ut.w);

        float4 un;
        {
            float num = a * ut.x * e;
            float den = fmaf(bc * ut.x, em1, a);
            un.x = (fabsf(den) > 1e-12f) ? (num / den) : ut.x;
            num = a * ut.y * e;
            den = fmaf(bc * ut.y, em1, a);
            un.y = (fabsf(den) > 1e-12f) ? (num / den) : ut.y;
            num = a * ut.z * e;
            den = fmaf(bc * ut.z, em1, a);
            un.z = (fabsf(den) > 1e-12f) ? (num / den) : ut.z;
            num = a * ut.w * e;
            den = fmaf(bc * ut.w, em1, a);
            un.w = (fabsf(den) > 1e-12f) ? (num / den) : ut.w;
        }
        un.x = fminf(fmaxf(un.x, 0.0f), 1.0f);
        un.y = fminf(fmaxf(un.y, 0.0f), 1.0f);
        un.z = fminf(fmaxf(un.z, 0.0f), 1.0f);
        un.w = fminf(fmaxf(un.w, 0.0f), 1.0f);
        o4[j] = un;
    }
}

// ---------------------------------------------------------------------------

extern "C" void kernel_launch(void* const* d_in, const int* in_sizes, int n_in,
                              void* d_out, int out_size)
{
    const float* u   = (const float*)d_in[0];
    const float* D   = (const float*)d_in[1];
    const float* k   = (const float*)d_in[2];
    const float* aC  = (const float*)d_in[3];
    const float* C_t = (const float*)d_in[4];
    float* out = (float*)d_out;

    imexetd_cg_kernel<<<GBLK, TBLK>>>(u, D, k, aC, C_t, out);
}

// round 13
// speedup vs baseline: 1.1041x; 1.0900x over previous
#include <cuda_runtime.h>

// ---------------------------------------------------------------------------
// IMEX-ETD: CG-solve (I - DT*D*Lap_neumann) x = u, then pointwise ETD update.
// Round 13: identical structure to round 12 (moment-based Krylov CG, four
// simple single-stencil passes), ONE change: per-thread dot accumulators are
// FLOAT (<=54 terms each), converted to double only at block-reduce time.
// Rationale: rounds 3-12 were secretly throttled by B300's cut-down FP64
// pipe (F2F.F64 + DADD per element); per-element fp64 work is now ~0.
//   P1: r0 = DT*D*lap(u)            -> m00
//   P2: s0 = A r0                   -> m01, m11
//   P3: t  = A s0                   -> m12, m22
//   P4: v  = A t (registers only)   -> m02, m03, m13, m23
//   scalar 3-step CG trajectory from moments (double) -> c0,c1,c2
//   epilogue: out = ETD(u + c0 r0 + c1 s0 + c2 t)
// 18N traffic, 4 grid barriers, fixed pass count, deterministic.
// ---------------------------------------------------------------------------

#define N_ELEM   8388608     // 8 * 1 * 1024 * 1024
#define N4       2097152     // float4 count
#define ROW4     256         // float4s per row
#define GBLK     152
#define TBLK     1024
#define NTHREADS (GBLK * TBLK)

#define DT_C     0.1f
#define CG_TAU   0.015

__device__ float g_r0[N_ELEM];
__device__ float g_s0[N_ELEM];
__device__ float g_t [N_ELEM];

// moment partials: 0:m00 1:m01 2:m11 3:m12 4:m22 5:m02 6:m03 7:m13 8:m23
__device__ double g_pm[9][GBLK];

__device__ unsigned g_cnt = 0;
__device__ volatile unsigned g_gen = 0;

// ---------------------------------------------------------------------------

__device__ __forceinline__ void grid_bar() {
    __syncthreads();
    __threadfence();                       // release
    if (threadIdx.x == 0) {
        unsigned snap = g_gen;
        unsigned arrived = atomicAdd(&g_cnt, 1u);
        if (arrived == GBLK - 1) {
            g_cnt = 0;
            __threadfence();
            g_gen = snap + 1u;
        } else {
            while (g_gen == snap) { }
        }
    }
    __syncthreads();
    __threadfence();                       // acquire (CCTL.IVALL): L1 coherent
}

// float partial in, double tree (one F2F per thread -> negligible fp64 work)
__device__ __forceinline__ double block_reduce_f2d(float vf) {
    __shared__ double sh[32];
    double v = (double)vf;
    int lane = threadIdx.x & 31;
    int w    = threadIdx.x >> 5;
#pragma unroll
    for (int o = 16; o; o >>= 1) v += __shfl_down_sync(0xffffffffu, v, o);
    if (lane == 0) sh[w] = v;
    __syncthreads();
    if (w == 0) {
        v = sh[lane];
#pragma unroll
        for (int o = 16; o; o >>= 1) v += __shfl_down_sync(0xffffffffu, v, o);
    }
    return v;                              // valid on thread 0
}

__device__ __forceinline__ double sum_partials_d(const double* a) {
    __shared__ double tot;
    int t = threadIdx.x;
    if (t < 32) {
        double s = 0.0;
#pragma unroll
        for (int j = t; j < GBLK; j += 32) s += a[j];
#pragma unroll
        for (int o = 16; o; o >>= 1) s += __shfl_down_sync(0xffffffffu, s, o);
        if (t == 0) tot = s;
    }
    __syncthreads();
    return tot;
}

// ---------------------------------------------------------------------------

__device__ __forceinline__ float dot4f(float4 a, float4 b) {
    return fmaf(a.x, b.x, fmaf(a.y, b.y, fmaf(a.z, b.z, a.w * b.w)));
}

__device__ __forceinline__ float4 lap_mk(float4 c, float4 t, float4 b,
                                         float lf, float rt) {
    float4 L;
    L.x = fmaf(-4.0f, c.x, (lf  + c.y) + (t.x + b.x));
    L.y = fmaf(-4.0f, c.y, (c.x + c.z) + (t.y + b.y));
    L.z = fmaf(-4.0f, c.z, (c.y + c.w) + (t.z + b.z));
    L.w = fmaf(-4.0f, c.w, (c.z + rt ) + (t.w + b.w));
    return L;
}

// 5-point window at float4 index j (Neumann edge clamp), plain cached loads
struct Win { float4 c, t, b; float l, r; };

__device__ __forceinline__ Win load_win(const float* __restrict__ s, int j) {
    Win w;
    int x4 = j & (ROW4 - 1);
    int y  = (j >> 8) & 1023;
    const float4* s4 = (const float4*)s;
    w.c = s4[j];
    w.t = (y > 0)    ? s4[j - ROW4] : w.c;
    w.b = (y < 1023) ? s4[j + ROW4] : w.c;
    w.l = (x4 > 0)        ? s[4*j - 1] : w.c.x;
    w.r = (x4 < ROW4 - 1) ? s[4*j + 4] : w.c.w;
    return w;
}

// ---------------------------------------------------------------------------

__global__ void __launch_bounds__(TBLK, 1)
imexetd_cg_kernel(const float* __restrict__ u,
                  const float* __restrict__ D,
                  const float* __restrict__ kp,
                  const float* __restrict__ aCp,
                  const float* __restrict__ Ctp,
                  float* __restrict__ out)
{
    const int tid = blockIdx.x * TBLK + threadIdx.x;
    const float4* __restrict__ D4 = (const float4*)D;

    // ================= P1: r0 = DT*D*lap(u); m00 ==========================
    {
        float4* __restrict__ dst = (float4*)g_r0;
        float a00 = 0.0f;
        for (int j = tid; j < N4; j += NTHREADS) {
            Win w = load_win(u, j);
            float4 dd = __ldg(D4 + j);
            float4 lp = lap_mk(w.c, w.t, w.b, w.l, w.r);
            float4 rv;
            rv.x = DT_C * dd.x * lp.x;
            rv.y = DT_C * dd.y * lp.y;
            rv.z = DT_C * dd.z * lp.z;
            rv.w = DT_C * dd.w * lp.w;
            dst[j] = rv;
            a00 += dot4f(rv, rv);
        }
        double v = block_reduce_f2d(a00);
        if (threadIdx.x == 0) g_pm[0][blockIdx.x] = v;
    }
    grid_bar();

    // ================= P2: s0 = A r0; m01, m11 ============================
    {
        float4* __restrict__ dst = (float4*)g_s0;
        float a01 = 0.0f, a11 = 0.0f;
        for (int j = tid; j < N4; j += NTHREADS) {
            Win w = load_win(g_r0, j);
            float4 dd = __ldg(D4 + j);
            float4 lp = lap_mk(w.c, w.t, w.b, w.l, w.r);
            float4 sv;
            sv.x = fmaf(-DT_C * dd.x, lp.x, w.c.x);
            sv.y = fmaf(-DT_C * dd.y, lp.y, w.c.y);
            sv.z = fmaf(-DT_C * dd.z, lp.z, w.c.z);
            sv.w = fmaf(-DT_C * dd.w, lp.w, w.c.w);
            dst[j] = sv;
            a01 += dot4f(w.c, sv);
            a11 += dot4f(sv, sv);
        }
        double v0 = block_reduce_f2d(a01);
        __syncthreads();
        double v1 = block_reduce_f2d(a11);
        if (threadIdx.x == 0) {
            g_pm[1][blockIdx.x] = v0;
            g_pm[2][blockIdx.x] = v1;
        }
    }
    grid_bar();

    // ================= P3: t = A s0; m12, m22 =============================
    {
        float4* __restrict__ dst = (float4*)g_t;
        float a12 = 0.0f, a22 = 0.0f;
        for (int j = tid; j < N4; j += NTHREADS) {
            Win w = load_win(g_s0, j);
            float4 dd = __ldg(D4 + j);
            float4 lp = lap_mk(w.c, w.t, w.b, w.l, w.r);
            float4 tv;
            tv.x = fmaf(-DT_C * dd.x, lp.x, w.c.x);
            tv.y = fmaf(-DT_C * dd.y, lp.y, w.c.y);
            tv.z = fmaf(-DT_C * dd.z, lp.z, w.c.z);
            tv.w = fmaf(-DT_C * dd.w, lp.w, w.c.w);
            dst[j] = tv;
            a12 += dot4f(w.c, tv);
            a22 += dot4f(tv, tv);
        }
        double v0 = block_reduce_f2d(a12);
        __syncthreads();
        double v1 = block_reduce_f2d(a22);
        if (threadIdx.x == 0) {
            g_pm[3][blockIdx.x] = v0;
            g_pm[4][blockIdx.x] = v1;
        }
    }
    grid_bar();

    // ========= P4: v = A t (registers); m02, m03, m13, m23 ================
    {
        const float4* __restrict__ r04 = (const float4*)g_r0;
        const float4* __restrict__ s04 = (const float4*)g_s0;
        float a02 = 0.0f, a03 = 0.0f, a13 = 0.0f, a23 = 0.0f;
        for (int j = tid; j < N4; j += NTHREADS) {
            Win w = load_win(g_t, j);
            float4 dd = __ldg(D4 + j);
            float4 lp = lap_mk(w.c, w.t, w.b, w.l, w.r);
            float4 vv;
            vv.x = fmaf(-DT_C * dd.x, lp.x, w.c.x);
            vv.y = fmaf(-DT_C * dd.y, lp.y, w.c.y);
            vv.z = fmaf(-DT_C * dd.z, lp.z, w.c.z);
            vv.w = fmaf(-DT_C * dd.w, lp.w, w.c.w);
            float4 r0v = r04[j];
            float4 s0v = s04[j];
            a02 += dot4f(r0v, w.c);
            a03 += dot4f(r0v, vv);
            a13 += dot4f(s0v, vv);
            a23 += dot4f(w.c, vv);
        }
        double v0 = block_reduce_f2d(a02);
        __syncthreads();
        double v1 = block_reduce_f2d(a03);
        __syncthreads();
        double v2 = block_reduce_f2d(a13);
        __syncthreads();
        double v3 = block_reduce_f2d(a23);
        if (threadIdx.x == 0) {
            g_pm[5][blockIdx.x] = v0;
            g_pm[6][blockIdx.x] = v1;
            g_pm[7][blockIdx.x] = v2;
            g_pm[8][blockIdx.x] = v3;
        }
    }
    grid_bar();

    // ========== scalar CG trajectory from moments (deterministic) =========
    double m00 = sum_partials_d(g_pm[0]);
    double m01 = sum_partials_d(g_pm[1]);
    double m11 = sum_partials_d(g_pm[2]);
    double m12 = sum_partials_d(g_pm[3]);
    double m22 = sum_partials_d(g_pm[4]);
    double m02 = sum_partials_d(g_pm[5]);
    double m03 = sum_partials_d(g_pm[6]);
    double m13 = sum_partials_d(g_pm[7]);
    double m23 = sum_partials_d(g_pm[8]);

    double M[4][4];
    M[0][0] = m00; M[0][1] = m01; M[0][2] = m02; M[0][3] = m03;
    M[1][0] = m01; M[1][1] = m11; M[1][2] = m12; M[1][3] = m13;
    M[2][0] = m02; M[2][1] = m12; M[2][2] = m22; M[2][3] = m23;
    M[3][0] = m03; M[3][1] = m13; M[3][2] = m23; M[3][3] = 0.0;  // never used

    double rv[4] = {1.0, 0.0, 0.0, 0.0};
    double pv[4] = {1.0, 0.0, 0.0, 0.0};
    double xv[4] = {0.0, 0.0, 0.0, 0.0};
    double rs = m00;

    for (int step = 0; step < 3; step++) {
        double Apv[4] = {0.0, pv[0], pv[1], pv[2]};   // A shifts Krylov index
        double pAp = 0.0;
#pragma unroll
        for (int i = 0; i < 4; i++)
#pragma unroll
            for (int jq = 0; jq < 4; jq++)
                pAp += pv[i] * M[i][jq] * Apv[jq];
        float af = (float)(rs / (pAp + 1e-300));
        double ad = (double)af;
#pragma unroll
        for (int i = 0; i < 4; i++) {
            xv[i] += ad * pv[i];
            rv[i] -= ad * Apv[i];
        }
        if (step == 2) break;              // rv degree 3; m33 unknown -> stop
        double rs_new = 0.0;
#pragma unroll
        for (int i = 0; i < 4; i++)
#pragma unroll
            for (int jq = 0; jq < 4; jq++)
                rs_new += rv[i] * M[i][jq] * rv[jq];
        if (rs_new < 0.0) rs_new = 0.0;
        if (sqrt(rs_new) < CG_TAU) break;
        float bf = (float)(rs_new / (rs + 1e-300));
        double bd = (double)bf;
#pragma unroll
        for (int i = 0; i < 4; i++) pv[i] = rv[i] + bd * pv[i];
        rs = rs_new;
    }
    float c0 = (float)xv[0];
    float c1 = (float)xv[1];
    float c2 = (float)xv[2];

    // ========== epilogue: u_tilde = u + c0 r0 + c1 s0 + c2 t; ETD =========
    float kk = __ldg(&kp[0]);
    float a  = kk - __ldg(&aCp[0]) * __ldg(&Ctp[0]);
    float bc = kk;                               // k / K_CAP, K_CAP = 1
    float adc = fminf(fmaxf(a * DT_C, -60.0f), 60.0f);
    float e   = expf(adc);
    float em1 = e - 1.0f;

    const float4* __restrict__ u4  = (const float4*)u;
    const float4* __restrict__ r04 = (const float4*)g_r0;
    const float4* __restrict__ s04 = (const float4*)g_s0;
    const float4* __restrict__ t4  = (const float4*)g_t;
    float4* __restrict__ o4 = (float4*)out;

    for (int j = tid; j < N4; j += NTHREADS) {
        float4 ut = __ldg(u4 + j);
        float4 rv0 = r04[j];
        float4 sv0 = s04[j];
        float4 tv0 = t4[j];
        ut.x = fmaf(c0, rv0.x, ut.x);
        ut.y = fmaf(c0, rv0.y, ut.y);
        ut.z = fmaf(c0, rv0.z, ut.z);
        ut.w = fmaf(c0, rv0.w, ut.w);
        ut.x = fmaf(c1, sv0.x, ut.x);
        ut.y = fmaf(c1, sv0.y, ut.y);
        ut.z = fmaf(c1, sv0.z, ut.z);
        ut.w = fmaf(c1, sv0.w, ut.w);
        ut.x = fmaf(c2, tv0.x, ut.x);
        ut.y = fmaf(c2, tv0.y, ut.y);
        ut.z = fmaf(c2, tv0.z, ut.z);
        ut.w = fmaf(c2, tv0.w, ut.w);

        float4 un;
        {
            float num = a * ut.x * e;
            float den = fmaf(bc * ut.x, em1, a);
            un.x = (fabsf(den) > 1e-12f) ? (num / den) : ut.x;
            num = a * ut.y * e;
            den = fmaf(bc * ut.y, em1, a);
            un.y = (fabsf(den) > 1e-12f) ? (num / den) : ut.y;
            num = a * ut.z * e;
            den = fmaf(bc * ut.z, em1, a);
            un.z = (fabsf(den) > 1e-12f) ? (num / den) : ut.z;
            num = a * ut.w * e;
            den = fmaf(bc * ut.w, em1, a);
            un.w = (fabsf(den) > 1e-12f) ? (num / den) : ut.w;
        }
        un.x = fminf(fmaxf(un.x, 0.0f), 1.0f);
        un.y = fminf(fmaxf(un.y, 0.0f), 1.0f);
        un.z = fminf(fmaxf(un.z, 0.0f), 1.0f);
        un.w = fminf(fmaxf(un.w, 0.0f), 1.0f);
        o4[j] = un;
    }
}

// ---------------------------------------------------------------------------

extern "C" void kernel_launch(void* const* d_in, const int* in_sizes, int n_in,
                              void* d_out, int out_size)
{
    const float* u   = (const float*)d_in[0];
    const float* D   = (const float*)d_in[1];
    const float* k   = (const float*)d_in[2];
    const float* aC  = (const float*)d_in[3];
    const float* C_t = (const float*)d_in[4];
    float* out = (float*)d_out;

    imexetd_cg_kernel<<<GBLK, TBLK>>>(u, D, k, aC, C_t, out);
}

// round 14
// speedup vs baseline: 1.5431x; 1.3976x over previous
#include <cuda_runtime.h>

// ---------------------------------------------------------------------------
// IMEX-ETD: CG-solve (I - DT*D*Lap_neumann) x = u, then pointwise ETD update.
// Round 14: moment-based Krylov CG (rounds 11-13 algebra) as SIX GRAPH-
// CAPTURED KERNEL LAUNCHES instead of one persistent kernel:
//   K1: r0 = DT*D*lap(u)                     -> m00 partials
//   K2: s0 = A r0                            -> m01, m11
//   K3: t  = A s0                            -> m12, m22
//   K4: v  = A t (registers only)            -> m02, m03, m13, m23
//   K5: (1 block) sum partials, run 3-step CG trajectory in double -> c0..c2
//   K6: out = ETD(u + c0 r0 + c1 s0 + c2 t)
// Wins vs persistent: free global sync (no spin barriers / fences), per-pass
// register allocation (higher occupancy), pure __ldg read-only paths.
// Deterministic: fixed-order reductions, fixed pass count.
// ---------------------------------------------------------------------------

#define N_ELEM   8388608     // 8 * 1 * 1024 * 1024
#define N4       2097152     // float4 count
#define ROW4     256         // float4s per row
#define PBLK     1024        // pass-kernel grid
#define PTHR     256         // pass-kernel block
#define PNTH     (PBLK * PTHR)

#define DT_C     0.1f
#define CG_TAU   0.015

__device__ float g_r0[N_ELEM];
__device__ float g_s0[N_ELEM];
__device__ float g_t [N_ELEM];

// moment partials: 0:m00 1:m01 2:m11 3:m12 4:m22 5:m02 6:m03 7:m13 8:m23
__device__ double g_pm[9][PBLK];
__device__ float  g_c[4];          // c0, c1, c2 (+pad)

// ---------------------------------------------------------------------------

__device__ __forceinline__ float dot4f(float4 a, float4 b) {
    return fmaf(a.x, b.x, fmaf(a.y, b.y, fmaf(a.z, b.z, a.w * b.w)));
}

__device__ __forceinline__ float4 lap_mk(float4 c, float4 t, float4 b,
                                         float lf, float rt) {
    float4 L;
    L.x = fmaf(-4.0f, c.x, (lf  + c.y) + (t.x + b.x));
    L.y = fmaf(-4.0f, c.y, (c.x + c.z) + (t.y + b.y));
    L.z = fmaf(-4.0f, c.z, (c.y + c.w) + (t.z + b.z));
    L.w = fmaf(-4.0f, c.w, (c.z + rt ) + (t.w + b.w));
    return L;
}

// 5-point window (Neumann clamp) via read-only cache
struct Win { float4 c, t, b; float l, r; };

__device__ __forceinline__ Win load_win(const float* __restrict__ s, int j) {
    Win w;
    int x4 = j & (ROW4 - 1);
    int y  = (j >> 8) & 1023;
    const float4* s4 = (const float4*)s;
    w.c = __ldg(s4 + j);
    w.t = (y > 0)    ? __ldg(s4 + (j - ROW4)) : w.c;
    w.b = (y < 1023) ? __ldg(s4 + (j + ROW4)) : w.c;
    w.l = (x4 > 0)        ? __ldg(s + 4*j - 1) : w.c.x;
    w.r = (x4 < ROW4 - 1) ? __ldg(s + 4*j + 4) : w.c.w;
    return w;
}

// float accumulator in, fixed-order double tree out (thread 0 valid)
__device__ __forceinline__ double block_reduce_f2d(float vf) {
    __shared__ double sh[PTHR / 32];
    double v = (double)vf;
    int lane = threadIdx.x & 31;
    int w    = threadIdx.x >> 5;
#pragma unroll
    for (int o = 16; o; o >>= 1) v += __shfl_down_sync(0xffffffffu, v, o);
    if (lane == 0) sh[w] = v;
    __syncthreads();
    if (w == 0) {
        v = (lane < PTHR / 32) ? sh[lane] : 0.0;
#pragma unroll
        for (int o = 16; o; o >>= 1) v += __shfl_down_sync(0xffffffffu, v, o);
    }
    return v;
}

// ---------------------------------------------------------------------------
// K1: r0 = DT*D*lap(u); m00

__global__ void __launch_bounds__(PTHR) k_r0(const float* __restrict__ u,
                                             const float* __restrict__ D)
{
    const int tid = blockIdx.x * PTHR + threadIdx.x;
    const float4* __restrict__ D4 = (const float4*)D;
    float4* __restrict__ dst = (float4*)g_r0;
    float a00 = 0.0f;
    for (int j = tid; j < N4; j += PNTH) {
        Win w = load_win(u, j);
        float4 dd = __ldg(D4 + j);
        float4 lp = lap_mk(w.c, w.t, w.b, w.l, w.r);
        float4 rv;
        rv.x = DT_C * dd.x * lp.x;
        rv.y = DT_C * dd.y * lp.y;
        rv.z = DT_C * dd.z * lp.z;
        rv.w = DT_C * dd.w * lp.w;
        dst[j] = rv;
        a00 += dot4f(rv, rv);
    }
    double v = block_reduce_f2d(a00);
    if (threadIdx.x == 0) g_pm[0][blockIdx.x] = v;
}

// K2: s0 = A r0; m01, m11
__global__ void __launch_bounds__(PTHR) k_s0(const float* __restrict__ D)
{
    const int tid = blockIdx.x * PTHR + threadIdx.x;
    const float4* __restrict__ D4 = (const float4*)D;
    float4* __restrict__ dst = (float4*)g_s0;
    float a01 = 0.0f, a11 = 0.0f;
    for (int j = tid; j < N4; j += PNTH) {
        Win w = load_win(g_r0, j);
        float4 dd = __ldg(D4 + j);
        float4 lp = lap_mk(w.c, w.t, w.b, w.l, w.r);
        float4 sv;
        sv.x = fmaf(-DT_C * dd.x, lp.x, w.c.x);
        sv.y = fmaf(-DT_C * dd.y, lp.y, w.c.y);
        sv.z = fmaf(-DT_C * dd.z, lp.z, w.c.z);
        sv.w = fmaf(-DT_C * dd.w, lp.w, w.c.w);
        dst[j] = sv;
        a01 += dot4f(w.c, sv);
        a11 += dot4f(sv, sv);
    }
    double v0 = block_reduce_f2d(a01);
    __syncthreads();
    double v1 = block_reduce_f2d(a11);
    if (threadIdx.x == 0) {
        g_pm[1][blockIdx.x] = v0;
        g_pm[2][blockIdx.x] = v1;
    }
}

// K3: t = A s0; m12, m22
__global__ void __launch_bounds__(PTHR) k_t(const float* __restrict__ D)
{
    const int tid = blockIdx.x * PTHR + threadIdx.x;
    const float4* __restrict__ D4 = (const float4*)D;
    float4* __restrict__ dst = (float4*)g_t;
    float a12 = 0.0f, a22 = 0.0f;
    for (int j = tid; j < N4; j += PNTH) {
        Win w = load_win(g_s0, j);
        float4 dd = __ldg(D4 + j);
        float4 lp = lap_mk(w.c, w.t, w.b, w.l, w.r);
        float4 tv;
        tv.x = fmaf(-DT_C * dd.x, lp.x, w.c.x);
        tv.y = fmaf(-DT_C * dd.y, lp.y, w.c.y);
        tv.z = fmaf(-DT_C * dd.z, lp.z, w.c.z);
        tv.w = fmaf(-DT_C * dd.w, lp.w, w.c.w);
        dst[j] = tv;
        a12 += dot4f(w.c, tv);
        a22 += dot4f(tv, tv);
    }
    double v0 = block_reduce_f2d(a12);
    __syncthreads();
    double v1 = block_reduce_f2d(a22);
    if (threadIdx.x == 0) {
        g_pm[3][blockIdx.x] = v0;
        g_pm[4][blockIdx.x] = v1;
    }
}

// K4: v = A t (registers only); m02, m03, m13, m23
__global__ void __launch_bounds__(PTHR) k_v(const float* __restrict__ D)
{
    const int tid = blockIdx.x * PTHR + threadIdx.x;
    const float4* __restrict__ D4 = (const float4*)D;
    const float4* __restrict__ r04 = (const float4*)g_r0;
    const float4* __restrict__ s04 = (const float4*)g_s0;
    float a02 = 0.0f, a03 = 0.0f, a13 = 0.0f, a23 = 0.0f;
    for (int j = tid; j < N4; j += PNTH) {
        Win w = load_win(g_t, j);
        float4 dd = __ldg(D4 + j);
        float4 lp = lap_mk(w.c, w.t, w.b, w.l, w.r);
        float4 vv;
        vv.x = fmaf(-DT_C * dd.x, lp.x, w.c.x);
        vv.y = fmaf(-DT_C * dd.y, lp.y, w.c.y);
        vv.z = fmaf(-DT_C * dd.z, lp.z, w.c.z);
        vv.w = fmaf(-DT_C * dd.w, lp.w, w.c.w);
        float4 r0v = __ldg(r04 + j);
        float4 s0v = __ldg(s04 + j);
        a02 += dot4f(r0v, w.c);
        a03 += dot4f(r0v, vv);
        a13 += dot4f(s0v, vv);
        a23 += dot4f(w.c, vv);
    }
    double v0 = block_reduce_f2d(a02);
    __syncthreads();
    double v1 = block_reduce_f2d(a03);
    __syncthreads();
    double v2 = block_reduce_f2d(a13);
    __syncthreads();
    double v3 = block_reduce_f2d(a23);
    if (threadIdx.x == 0) {
        g_pm[5][blockIdx.x] = v0;
        g_pm[6][blockIdx.x] = v1;
        g_pm[7][blockIdx.x] = v2;
        g_pm[8][blockIdx.x] = v3;
    }
}

// ---------------------------------------------------------------------------
// K5 (1 block, 1024 threads): sum partials (warp q sums moment q), then run
// the 3-step CG trajectory in double, write coefficients.

__global__ void __launch_bounds__(1024) k_coef()
{
    __shared__ double mom[9];
    int lane = threadIdx.x & 31;
    int w    = threadIdx.x >> 5;
    if (w < 9) {
        double s = 0.0;
        for (int j = lane; j < PBLK; j += 32) s += g_pm[w][j];
#pragma unroll
        for (int o = 16; o; o >>= 1) s += __shfl_down_sync(0xffffffffu, s, o);
        if (lane == 0) mom[w] = s;
    }
    __syncthreads();
    if (threadIdx.x == 0) {
        double m00 = mom[0], m01 = mom[1], m11 = mom[2];
        double m12 = mom[3], m22 = mom[4], m02 = mom[5];
        double m03 = mom[6], m13 = mom[7], m23 = mom[8];

        double M[4][4];
        M[0][0] = m00; M[0][1] = m01; M[0][2] = m02; M[0][3] = m03;
        M[1][0] = m01; M[1][1] = m11; M[1][2] = m12; M[1][3] = m13;
        M[2][0] = m02; M[2][1] = m12; M[2][2] = m22; M[2][3] = m23;
        M[3][0] = m03; M[3][1] = m13; M[3][2] = m23; M[3][3] = 0.0;

        double rv[4] = {1.0, 0.0, 0.0, 0.0};
        double pv[4] = {1.0, 0.0, 0.0, 0.0};
        double xv[4] = {0.0, 0.0, 0.0, 0.0};
        double rs = m00;

        for (int step = 0; step < 3; step++) {
            double Apv[4] = {0.0, pv[0], pv[1], pv[2]};
            double pAp = 0.0;
            for (int i = 0; i < 4; i++)
                for (int jq = 0; jq < 4; jq++)
                    pAp += pv[i] * M[i][jq] * Apv[jq];
            float af = (float)(rs / (pAp + 1e-300));
            double ad = (double)af;
            for (int i = 0; i < 4; i++) {
                xv[i] += ad * pv[i];
                rv[i] -= ad * Apv[i];
            }
            if (step == 2) break;
            double rs_new = 0.0;
            for (int i = 0; i < 4; i++)
                for (int jq = 0; jq < 4; jq++)
                    rs_new += rv[i] * M[i][jq] * rv[jq];
            if (rs_new < 0.0) rs_new = 0.0;
            if (sqrt(rs_new) < CG_TAU) break;
            float bf = (float)(rs_new / (rs + 1e-300));
            double bd = (double)bf;
            for (int i = 0; i < 4; i++) pv[i] = rv[i] + bd * pv[i];
            rs = rs_new;
        }
        g_c[0] = (float)xv[0];
        g_c[1] = (float)xv[1];
        g_c[2] = (float)xv[2];
        g_c[3] = 0.0f;
    }
}

// ---------------------------------------------------------------------------
// K6: out = ETD(u + c0 r0 + c1 s0 + c2 t), clipped

__global__ void __launch_bounds__(PTHR) k_etd(const float* __restrict__ u,
                                              const float* __restrict__ kp,
                                              const float* __restrict__ aCp,
                                              const float* __restrict__ Ctp,
                                              float* __restrict__ out)
{
    const int tid = blockIdx.x * PTHR + threadIdx.x;
    float c0 = g_c[0], c1 = g_c[1], c2 = g_c[2];

    float kk = __ldg(&kp[0]);
    float a  = kk - __ldg(&aCp[0]) * __ldg(&Ctp[0]);
    float bc = kk;                               // k / K_CAP, K_CAP = 1
    float adc = fminf(fmaxf(a * DT_C, -60.0f), 60.0f);
    float e   = expf(adc);
    float em1 = e - 1.0f;

    const float4* __restrict__ u4  = (const float4*)u;
    const float4* __restrict__ r04 = (const float4*)g_r0;
    const float4* __restrict__ s04 = (const float4*)g_s0;
    const float4* __restrict__ t4  = (const float4*)g_t;
    float4* __restrict__ o4 = (float4*)out;

    for (int j = tid; j < N4; j += PNTH) {
        float4 ut = __ldg(u4 + j);
        float4 rv0 = __ldg(r04 + j);
        float4 sv0 = __ldg(s04 + j);
        float4 tv0 = __ldg(t4 + j);
        ut.x = fmaf(c0, rv0.x, ut.x);
        ut.y = fmaf(c0, rv0.y, ut.y);
        ut.z = fmaf(c0, rv0.z, ut.z);
        ut.w = fmaf(c0, rv0.w, ut.w);
        ut.x = fmaf(c1, sv0.x, ut.x);
        ut.y = fmaf(c1, sv0.y, ut.y);
        ut.z = fmaf(c1, sv0.z, ut.z);
        ut.w = fmaf(c1, sv0.w, ut.w);
        ut.x = fmaf(c2, tv0.x, ut.x);
        ut.y = fmaf(c2, tv0.y, ut.y);
        ut.z = fmaf(c2, tv0.z, ut.z);
        ut.w = fmaf(c2, tv0.w, ut.w);

        float4 un;
        {
            float num = a * ut.x * e;
            float den = fmaf(bc * ut.x, em1, a);
            un.x = (fabsf(den) > 1e-12f) ? (num / den) : ut.x;
            num = a * ut.y * e;
            den = fmaf(bc * ut.y, em1, a);
            un.y = (fabsf(den) > 1e-12f) ? (num / den) : ut.y;
            num = a * ut.z * e;
            den = fmaf(bc * ut.z, em1, a);
            un.z = (fabsf(den) > 1e-12f) ? (num / den) : ut.z;
            num = a * ut.w * e;
            den = fmaf(bc * ut.w, em1, a);
            un.w = (fabsf(den) > 1e-12f) ? (num / den) : ut.w;
        }
        un.x = fminf(fmaxf(un.x, 0.0f), 1.0f);
        un.y = fminf(fmaxf(un.y, 0.0f), 1.0f);
        un.z = fminf(fmaxf(un.z, 0.0f), 1.0f);
        un.w = fminf(fmaxf(un.w, 0.0f), 1.0f);
        o4[j] = un;
    }
}

// ---------------------------------------------------------------------------

extern "C" void kernel_launch(void* const* d_in, const int* in_sizes, int n_in,
                              void* d_out, int out_size)
{
    const float* u   = (const float*)d_in[0];
    const float* D   = (const float*)d_in[1];
    const float* k   = (const float*)d_in[2];
    const float* aC  = (const float*)d_in[3];
    const float* C_t = (const float*)d_in[4];
    float* out = (float*)d_out;

    k_r0  <<<PBLK, PTHR>>>(u, D);
    k_s0  <<<PBLK, PTHR>>>(D);
    k_t   <<<PBLK, PTHR>>>(D);
    k_v   <<<PBLK, PTHR>>>(D);
    k_coef<<<1, 1024>>>();
    k_etd <<<PBLK, PTHR>>>(u, k, aC, C_t, out);
}